// round 3
// baseline (speedup 1.0000x reference)
#include <cuda_runtime.h>

#define NMAX      16384
#define TPB       256
#define RPT       8                    // rows per thread
#define ROWS_BLK  (TPB * RPT)          // 2048 rows per block
#define TILE      128                  // columns staged in smem per tile
#define YCHUNKS   74                   // 8 x 74 = 592 blocks = 148 SMs x 4 resident

__device__ float g_minA[NMAX];  // per pred row i: min_j 0.5*d2(i,j)
__device__ float g_minB[NMAX];  // per gt col j:  min_i (0.5||x_i||^2 - x_i.y_j)  (= 0.5*d2min - 0.5||y_j||^2)

__device__ __forceinline__ float inf_f() { return __int_as_float(0x7f800000); }

__global__ void init_kernel(int np, int ng) {
    int i = blockIdx.x * blockDim.x + threadIdx.x;
    if (i < np) g_minA[i] = inf_f();
    if (i < ng) g_minB[i] = inf_f();
}

// Mixed-sign atomic float min (works for global and shared):
// positives via signed int-min, negatives via uint-max. Init must be +INF.
__device__ __forceinline__ void atomicMinF(float* addr, float val) {
    if (val >= 0.0f) atomicMin((int*)addr, __float_as_int(val));
    else             atomicMax((unsigned int*)addr, __float_as_uint(val));
}

// Single sweep over the 16384x16384 implicit d2 matrix.
// Rows = pred points, cols = gt points.
//   s_ij = 0.5||x_i||^2 - x_i.y_j           (3 FFMA, init from register h_i)
//   row quantity: s + 0.5||y_j||^2 = 0.5*d2 (1 FADD) -> rowmin
//   col quantity: s itself                   -> colmin (tree + shfl + 1-lane ATOMS)
__global__ void __launch_bounds__(TPB, 4)
pass_kernel(const float* __restrict__ P, const float* __restrict__ G,
            int NP, int NG) {
    __shared__ float4 sy[TILE];
    __shared__ float  colminS[TILE];

    const int tid  = threadIdx.x;
    const int lane = tid & 31;
    const int row0 = blockIdx.x * ROWS_BLK + tid;

    float nx0[RPT], nx1[RPT], nx2[RPT], h[RPT], rowmin[RPT];
#pragma unroll
    for (int p = 0; p < RPT; p++) {
        int r = row0 + p * TPB;
        if (r < NP) {
            float a = P[3*r], b = P[3*r+1], c = P[3*r+2];
            nx0[p] = -a; nx1[p] = -b; nx2[p] = -c;
            h[p] = 0.5f * (a*a + b*b + c*c);
        } else {
            nx0[p] = 0.f; nx1[p] = 0.f; nx2[p] = 0.f;
            h[p] = inf_f();                 // invalid row -> s = +INF, never wins colmin
        }
        rowmin[p] = inf_f();
    }

    const int chunk = (NG + YCHUNKS - 1) / YCHUNKS;
    const int yb = blockIdx.y * chunk;
    const int ye = min(yb + chunk, NG);

    for (int t0 = yb; t0 < ye; t0 += TILE) {
        const int tn = min(TILE, ye - t0);
        __syncthreads();
        for (int j = tid; j < tn; j += TPB) {
            int g = t0 + j;
            float a = G[3*g], b = G[3*g+1], c = G[3*g+2];
            sy[j] = make_float4(a, b, c, 0.5f * (a*a + b*b + c*c));
            colminS[j] = inf_f();
        }
        __syncthreads();

#pragma unroll 2
        for (int j = 0; j < tn; j++) {
            const float4 y = sy[j];            // one LDS.128 broadcast
            float s[RPT];
#pragma unroll
            for (int p = 0; p < RPT; p++) {
                float t = fmaf(nx2[p], y.z, h[p]);
                t = fmaf(nx1[p], y.y, t);
                t = fmaf(nx0[p], y.x, t);
                s[p] = t;
                rowmin[p] = fminf(rowmin[p], t + y.w);   // 0.5*d2
            }
            // col-min: tree over this thread's 8 rows
            float m01 = fminf(s[0], s[1]), m23 = fminf(s[2], s[3]);
            float m45 = fminf(s[4], s[5]), m67 = fminf(s[6], s[7]);
            float cm = fminf(fminf(m01, m23), fminf(m45, m67));
            // warp reduce (lanes hold distinct rows)
#pragma unroll
            for (int o = 16; o > 0; o >>= 1)
                cm = fminf(cm, __shfl_down_sync(0xffffffffu, cm, o));
            if (lane == 0) atomicMinF(&colminS[j], cm);
        }

        __syncthreads();
        for (int j = tid; j < tn; j += TPB)
            atomicMinF(&g_minB[t0 + j], colminS[j]);
    }

#pragma unroll
    for (int p = 0; p < RPT; p++) {
        int r = row0 + p * TPB;
        if (r < NP) atomicMinF(&g_minA[r], rowmin[p]);
    }
}

__global__ void finalize_kernel(const float* __restrict__ G,
                                int NP, int NG, float* __restrict__ out) {
    __shared__ float ssum[32];
    const int tid = threadIdx.x;
    const float wP = 1.0f / (float)NP;
    const float wG = 1.0f / (float)NG;
    float acc = 0.f;

    for (int i = tid; i < NP; i += blockDim.x) {
        float d2 = 2.0f * g_minA[i];                       // rowmin already = 0.5*d2
        acc += sqrtf(fmaxf(d2, 0.f)) * wP;
    }
    for (int j = tid; j < NG; j += blockDim.x) {
        float a = G[3*j], b = G[3*j+1], c = G[3*j+2];
        float cj = 0.5f * (a*a + b*b + c*c);
        float d2 = 2.0f * (g_minB[j] + cj);
        acc += sqrtf(fmaxf(d2, 0.f)) * wG;
    }

#pragma unroll
    for (int o = 16; o > 0; o >>= 1) acc += __shfl_down_sync(0xffffffffu, acc, o);
    if ((tid & 31) == 0) ssum[tid >> 5] = acc;
    __syncthreads();
    if (tid < 32) {
        int nwarps = (blockDim.x + 31) >> 5;
        float v = (tid < nwarps) ? ssum[tid] : 0.f;
#pragma unroll
        for (int o = 16; o > 0; o >>= 1) v += __shfl_down_sync(0xffffffffu, v, o);
        if (tid == 0) out[0] = v;
    }
}

extern "C" void kernel_launch(void* const* d_in, const int* in_sizes, int n_in,
                              void* d_out, int out_size) {
    const float* P = (const float*)d_in[0];
    const float* G = (const float*)d_in[1];
    const int NP = in_sizes[0] / 3;
    const int NG = in_sizes[1] / 3;
    float* out = (float*)d_out;

    const int nmax = NP > NG ? NP : NG;
    init_kernel<<<(nmax + 255) / 256, 256>>>(NP, NG);

    dim3 grid((NP + ROWS_BLK - 1) / ROWS_BLK, YCHUNKS, 1);
    pass_kernel<<<grid, TPB>>>(P, G, NP, NG);

    finalize_kernel<<<1, 512>>>(G, NP, NG, out);
}